// round 15
// baseline (speedup 1.0000x reference)
#include <cuda_runtime.h>
#include <cuda_fp16.h>
#include <math.h>

#define NB 16
#define NC 256
#define PLANE 3136
#define NPLANES 4096
typedef unsigned long long ull;

// scratch (static device globals; no allocation)
__device__ __half g_xfuse[NPLANES * PLANE];  // 25.7 MB (fp16 activations)
__device__ float g_pool2[NB * 2 * 28 * NC];  // partial pools [b][half][bin][c]
__device__ float g_h[NB * 50 * 64];          // hidden layer (pos 49 = mean)
__device__ float g_wdyn[NB * 49 * NC];       // [B][pos][C]
__device__ float g_bdyn[NB * NC];            // [B][C]
__device__ float g_pw1T[256 * 64];           // [k][o]
__device__ float g_pw2T[64 * 1024];          // [k][oc]
__device__ float g_w1T[49 * 1024];           // [pos][g*C+c]

__device__ __forceinline__ void ffma2(ull& d, ull a, ull b) {
    asm("fma.rn.f32x2 %0, %1, %2, %0;" : "+l"(d) : "l"(a), "l"(b));
}
__device__ __forceinline__ float2 u2f2(ull v) {
    float2 r;
    r.x = __uint_as_float((unsigned)v);
    r.y = __uint_as_float((unsigned)(v >> 32));
    return r;
}
// half2 (packed in u32) -> f32x2 pair (packed in u64) for ffma2
__device__ __forceinline__ ull h2f2(unsigned h) {
    ull r;
    asm("{\n\t"
        ".reg .b16 l,h;\n\t"
        ".reg .f32 fl,fh;\n\t"
        "mov.b32 {l,h}, %1;\n\t"
        "cvt.f32.f16 fl, l;\n\t"
        "cvt.f32.f16 fh, h;\n\t"
        "mov.b64 %0, {fl,fh};\n\t"
        "}" : "=l"(r) : "r"(h));
    return r;
}

// ---------------------------------------------------------------------------
// Kernel 1: fused dw3x3+BN (x2), relu6 gate, x_fuse (fp16 out), partial pool.
// HALF-PLANE blocks (224 thr, 28 rows, tile 30x66), lane = row, conflict-
// free LDS.64, po-recombine mainloop (R9-proven). Pooling stays fp32.
// Blocks >= 2*NPLANES perform the small weight transposes.
// ---------------------------------------------------------------------------
__global__ __launch_bounds__(224, 6) void k_fuse(
    const float* __restrict__ x1,
    const float* __restrict__ dw1_w, const float* __restrict__ dw1_g,
    const float* __restrict__ dw1_b, const float* __restrict__ dw1_m,
    const float* __restrict__ dw1_v,
    const float* __restrict__ dw2_w, const float* __restrict__ dw2_g,
    const float* __restrict__ dw2_b, const float* __restrict__ dw2_m,
    const float* __restrict__ dw2_v,
    const float* __restrict__ pw1, const float* __restrict__ pw2,
    const float* __restrict__ w1grp) {
    const int tid = threadIdx.x;

    if (blockIdx.x >= 2 * NPLANES) {       // transpose side-work
        int i = (blockIdx.x - 2 * NPLANES) * 224 + tid;
        if (i < 16384) {                   // pw1 [64,256] -> [256,64]
            int k = i >> 6, o = i & 63;
            g_pw1T[i] = pw1[o * 256 + k];
        } else if (i < 81920) {            // pw2 [1024,64] -> [64,1024]
            int j = i - 16384;
            int k = j >> 10, oc = j & 1023;
            g_pw2T[j] = pw2[oc * 64 + k];
        } else if (i < 132096) {           // weight1 [G*C,49] -> [49,G*C]
            int l = i - 81920;
            int pos = l / 1024, gc = l & 1023;
            g_w1T[l] = w1grp[gc * 49 + pos];
        }
        return;
    }

    __shared__ float s[30 * 66];           // half tile, halo 1, stride 66
    __shared__ float2 sw1[9], sw2[9];      // packed (w,w) weights
    __shared__ float partial[196];

    const int bp = blockIdx.x >> 1;
    const int half = blockIdx.x & 1;       // 0: rows 0..27, 1: rows 28..55
    const int b = bp >> 8, c = bp & 255;
    const int base = half * 28;

    // column halo: x in {0,57} for all 30 tile rows
    if (tid < 60) {
        int r = tid >> 1, x = (tid & 1) ? 57 : 0;
        s[r * 66 + x] = 0.f;
    }
    {
        const float4* __restrict__ xp4 =
            (const float4*)(x1 + (size_t)bp * PLANE);
        for (int idx = tid; idx < 420; idx += 224) {   // 30 rows x 14 f4
            int r = idx / 14, c4 = idx - r * 14;
            int gr = base - 1 + r;
            float4 v = make_float4(0.f, 0.f, 0.f, 0.f);
            if ((unsigned)gr < 56u) v = xp4[gr * 14 + c4];
            float* d = &s[r * 66 + 1 + c4 * 4];
            d[0] = v.x; d[1] = v.y; d[2] = v.z; d[3] = v.w;
        }
    }
    // BN-folded channel scalars
    const float s1 = dw1_g[c] * rsqrtf(dw1_v[c] + 1e-5f);
    const float s2 = dw2_g[c] * rsqrtf(dw2_v[c] + 1e-5f);
    const float bb1 = dw1_b[c] - dw1_m[c] * s1;
    const float bb2 = dw2_b[c] - dw2_m[c] * s2;
    if (tid < 9) {
        float wa = dw1_w[c * 9 + tid] * s1;
        float wb = dw2_w[c * 9 + tid] * s2;
        sw1[tid] = make_float2(wa, wa);
        sw2[tid] = make_float2(wb, wb);
    }
    __syncthreads();

    const int lane = tid & 31;
    const int cg = tid >> 5;               // 0..6
    if (lane < 28) {
        ull aA[4] = {0, 0, 0, 0}, aB[4] = {0, 0, 0, 0};
#pragma unroll
        for (int ky = 0; ky < 3; ky++) {
            const float* rp = &s[(lane + ky) * 66 + cg * 8];
            ull pe[5];
#pragma unroll
            for (int k = 0; k < 5; k++) pe[k] = *(const ull*)(rp + 2 * k);
            ull po[4];
#pragma unroll
            for (int m = 0; m < 4; m++)
                po[m] = (pe[m] >> 32) | (pe[m + 1] << 32);
#pragma unroll
            for (int t = 0; t < 2; t++) {   // kx = 0, 2
                ull wa = *(const ull*)&sw1[ky * 3 + 2 * t];
                ull wb = *(const ull*)&sw2[ky * 3 + 2 * t];
#pragma unroll
                for (int j = 0; j < 4; j++) {
                    ffma2(aA[j], wa, pe[j + t]);
                    ffma2(aB[j], wb, pe[j + t]);
                }
            }
            {                               // kx = 1
                ull wa = *(const ull*)&sw1[ky * 3 + 1];
                ull wb = *(const ull*)&sw2[ky * 3 + 1];
#pragma unroll
                for (int j = 0; j < 4; j++) {
                    ffma2(aA[j], wa, po[j]);
                    ffma2(aB[j], wb, po[j]);
                }
            }
        }
        float f[8];
        float rsum = 0.f;
#pragma unroll
        for (int j = 0; j < 4; j++) {
            float2 pa = u2f2(aA[j]), pb = u2f2(aB[j]);
            float a0 = fminf(fmaxf(pa.x + bb1, 0.f), 6.f);
            float a1 = fminf(fmaxf(pa.y + bb1, 0.f), 6.f);
            float v0 = a0 * (pb.x + bb2);
            float v1 = a1 * (pb.y + bb2);
            f[2 * j] = v0; f[2 * j + 1] = v1;
            rsum += v0 + v1;
        }
        const int row = base + lane;
        // pack 8 fp16 values -> one 16B store
        __half2 h01 = __floats2half2_rn(f[0], f[1]);
        __half2 h23 = __floats2half2_rn(f[2], f[3]);
        __half2 h45 = __floats2half2_rn(f[4], f[5]);
        __half2 h67 = __floats2half2_rn(f[6], f[7]);
        uint4 u;
        u.x = *(unsigned*)&h01; u.y = *(unsigned*)&h23;
        u.z = *(unsigned*)&h45; u.w = *(unsigned*)&h67;
        *(uint4*)(g_xfuse + (size_t)bp * PLANE + row * 56 + cg * 8) = u;
        partial[lane * 7 + cg] = rsum;     // pooling from fp32 values
    }
    __syncthreads();

    // partial pooling: 28 bins (4 local pool rows x 7 cols)
    if (tid < 28) {
        const int p = tid / 7, pc = tid - p * 7;
        int start, cnt;
        if (half == 0) { start = p * 8;                cnt = (p < 3) ? 8 : 4; }
        else           { start = (p == 0) ? 0 : p * 8 - 4; cnt = (p == 0) ? 4 : 8; }
        float sm = 0.f;
        for (int i = 0; i < cnt; i++) sm += partial[(start + i) * 7 + pc];
        g_pool2[((b * 2 + half) * 28 + tid) * NC + c] = sm;
    }
}

// ---------------------------------------------------------------------------
// Kernel 2a: hidden layer h = gelu(pw1 @ v + pb1) for all (b, pos).
// ---------------------------------------------------------------------------
__global__ __launch_bounds__(256) void k_dyn_h(const float* __restrict__ pb1) {
    __shared__ float v[10 * 256];

    const int pg = blockIdx.x, b = blockIdx.y, t = threadIdx.x;
    const int base = pg * 10;
    const int nload = (pg == 4) ? 9 : 10;

    for (int i = t; i < nload * 256; i += 256) {
        int pos = base + i / 256;
        int cc = i & 255;
        int pr = pos / 7, pc = pos - pr * 7;
        float val = 0.f;
        if (pr <= 3) val += g_pool2[((b * 2 + 0) * 28 + pr * 7 + pc) * NC + cc];
        if (pr >= 3) val += g_pool2[((b * 2 + 1) * 28 + (pr - 3) * 7 + pc) * NC + cc];
        v[i] = val * (1.f / 64.f);
    }
    if (pg == 4) {
        float sm = 0.f;
        for (int j = 0; j < 28; j++)
            sm += g_pool2[((b * 2 + 0) * 28 + j) * NC + t] +
                  g_pool2[((b * 2 + 1) * 28 + j) * NC + t];
        v[9 * 256 + t] = sm * (1.f / (64.f * 49.f));
    }
    __syncthreads();

    const int o = t & 63;
    for (int pl = t >> 6; pl < 10; pl += 4) {
        const float* vr = &v[pl * 256];
        float acc0 = 0.f, acc1 = 0.f;
#pragma unroll 8
        for (int k = 0; k < 256; k += 2) {
            acc0 += g_pw1T[k * 64 + o] * vr[k];
            acc1 += g_pw1T[(k + 1) * 64 + o] * vr[k + 1];
        }
        float x = acc0 + acc1 + pb1[o];
        g_h[(b * 50 + base + pl) * 64 + o] =
            0.5f * x * (1.f + erff(x * 0.70710678118654752f));
    }
}

// ---------------------------------------------------------------------------
// Kernel 2b: logits = h @ pw2 (+pb2), softmax over G, weighted sums.
// ---------------------------------------------------------------------------
__global__ __launch_bounds__(256) void k_dyn2(
    const float* __restrict__ pb2, const float* __restrict__ bias1) {
    __shared__ float hs[50 * 64];

    const int b = blockIdx.y, t = threadIdx.x;
    const int c = blockIdx.x * 32 + (t & 31);
    const int ps = t >> 5;                 // 0..7 pos stripe

    for (int i = t; i < 3200; i += 256) hs[i] = g_h[b * 3200 + i];
    __syncthreads();

    const int np = (ps < 2) ? 7 : 6;       // positions ps, ps+8, ...
    float acc[7][4];
#pragma unroll
    for (int i = 0; i < 7; i++)
#pragma unroll
        for (int g = 0; g < 4; g++) acc[i][g] = 0.f;

#pragma unroll 4
    for (int k = 0; k < 64; k++) {
        const float w0 = g_pw2T[k * 1024 + c];
        const float w1 = g_pw2T[k * 1024 + 256 + c];
        const float w2 = g_pw2T[k * 1024 + 512 + c];
        const float w3 = g_pw2T[k * 1024 + 768 + c];
#pragma unroll
        for (int i = 0; i < 7; i++) {
            if (i < np) {
                const float h = hs[(ps + 8 * i) * 64 + k];
                acc[i][0] += h * w0;
                acc[i][1] += h * w1;
                acc[i][2] += h * w2;
                acc[i][3] += h * w3;
            }
        }
    }

    const float q0 = pb2[c], q1 = pb2[256 + c], q2 = pb2[512 + c], q3 = pb2[768 + c];
#pragma unroll
    for (int i = 0; i < 7; i++) {
        if (i >= np) break;
        const int pos = ps + 8 * i;
        float l0 = acc[i][0] + q0, l1 = acc[i][1] + q1;
        float l2 = acc[i][2] + q2, l3 = acc[i][3] + q3;
        float m = fmaxf(fmaxf(l0, l1), fmaxf(l2, l3));
        float e0 = expf(l0 - m), e1 = expf(l1 - m);
        float e2 = expf(l2 - m), e3 = expf(l3 - m);
        float inv = 1.f / (e0 + e1 + e2 + e3);
        if (pos < 49) {
            const float* wp = &g_w1T[pos * 1024];
            float wv = e0 * wp[c] + e1 * wp[256 + c] + e2 * wp[512 + c] +
                       e3 * wp[768 + c];
            g_wdyn[(b * 49 + pos) * NC + c] = wv * inv;
        } else {
            float bv = e0 * bias1[c] + e1 * bias1[256 + c] +
                       e2 * bias1[512 + c] + e3 * bias1[768 + c];
            g_bdyn[b * NC + c] = bv * inv;
        }
    }
}

// ---------------------------------------------------------------------------
// Kernel 3: dynamic 7x7 depthwise conv + dynamic bias. Half-plane blocks
// (R12 form) with FP16 smem tile: row reads 7xLDS.64 -> 4xLDS.64 per ky
// (-43% row wavefronts), conflict-free at half-stride 68 (bank = 2*lane+c).
// cvt.f32.f16 pairs feed the unchanged f32 FFMA2 / S-accumulator mainloop.
// ---------------------------------------------------------------------------
__global__ __launch_bounds__(224, 6) void k_conv(float* __restrict__ out) {
    __shared__ __half sh[34 * 68];         // half tile, halo 3, stride 68
    __shared__ __align__(16) float2 wsm2[56];  // (w,w), stride 8 per ky row
    __shared__ float bsm;

    const int bp = blockIdx.x >> 1;        // plane
    const int half = blockIdx.x & 1;       // 0: rows 0..27, 1: rows 28..55
    const int b = bp >> 8, c = bp & 255;
    const int base = half * 28;
    const int tid = threadIdx.x;

    // column-halo zeroing: cols {0,1,2} + {59..67} x 34 rows = 408 halfs
    for (int i = tid; i < 408; i += 224) {
        int r = i / 12, k = i - r * 12;
        int x = (k < 3) ? k : 56 + k;      // 0,1,2, 59..67
        sh[r * 68 + x] = __ushort_as_half(0);
    }
    {
        const uint4* __restrict__ xp4 =
            (const uint4*)(g_xfuse + (size_t)bp * PLANE);  // 8 halfs each
        for (int idx = tid; idx < 238; idx += 224) {   // 34 rows x 7 u4
            int r = idx / 7, c8 = idx - r * 7;
            int gr = base - 3 + r;
            uint4 v = make_uint4(0u, 0u, 0u, 0u);
            if ((unsigned)gr < 56u) v = xp4[gr * 7 + c8];
            __half* d = &sh[r * 68 + 3 + c8 * 8];
            const __half* src = (const __half*)&v;
#pragma unroll
            for (int k = 0; k < 8; k++) d[k] = src[k];
        }
    }
    if (tid < 49) {
        int ky = tid / 7, kx = tid - ky * 7;
        float w = g_wdyn[(b * 49 + tid) * NC + c];
        wsm2[ky * 8 + kx] = make_float2(w, w);
    }
    if (tid == 63) bsm = g_bdyn[b * NC + c];
    __syncthreads();

    const int lane = tid & 31;
    const int cg = tid >> 5;               // 0..6
    if (lane < 28) {
        const int row = base + lane;       // output row (global)
        ull acc[4] = {0, 0, 0, 0};
        ull S[5] = {0, 0, 0, 0, 0};
#pragma unroll
        for (int ky = 0; ky < 7; ky++) {
            const __half* rp = &sh[(lane + ky) * 68 + cg * 8];
            uint2 q0 = *(const uint2*)(rp);        // halfs 0..3
            uint2 q1 = *(const uint2*)(rp + 4);    // 4..7
            uint2 q2 = *(const uint2*)(rp + 8);    // 8..11
            uint2 q3 = *(const uint2*)(rp + 12);   // 12..15 (tail padded)
            ull pe[7];
            pe[0] = h2f2(q0.x); pe[1] = h2f2(q0.y);
            pe[2] = h2f2(q1.x); pe[3] = h2f2(q1.y);
            pe[4] = h2f2(q2.x); pe[5] = h2f2(q2.y);
            pe[6] = h2f2(q3.x);
            // vectorized weight fetch: kx pairs (0,1) (2,3) (4,5) + 6
            ulonglong2 wq0 = *(const ulonglong2*)&wsm2[ky * 8 + 0];
            ulonglong2 wq1 = *(const ulonglong2*)&wsm2[ky * 8 + 2];
            ulonglong2 wq2 = *(const ulonglong2*)&wsm2[ky * 8 + 4];
            ull w6 = *(const ull*)&wsm2[ky * 8 + 6];
            ull we[4] = {wq0.x, wq1.x, wq2.x, w6};    // kx = 0,2,4,6
            ull wo[3] = {wq0.y, wq1.y, wq2.y};        // kx = 1,3,5
#pragma unroll
            for (int t = 0; t < 4; t++)
#pragma unroll
                for (int j = 0; j < 4; j++) ffma2(acc[j], we[t], pe[j + t]);
#pragma unroll
            for (int t = 0; t < 3; t++)
#pragma unroll
                for (int i = 0; i < 5; i++) ffma2(S[i], wo[t], pe[i + t]);
        }
        const float bv = bsm;
        float2 a0 = u2f2(acc[0]), a1 = u2f2(acc[1]);
        float2 a2 = u2f2(acc[2]), a3 = u2f2(acc[3]);
        float2 s0 = u2f2(S[0]), s1 = u2f2(S[1]), s2 = u2f2(S[2]);
        float2 s3 = u2f2(S[3]), s4 = u2f2(S[4]);
        float4* op = (float4*)(out + (size_t)bp * PLANE + row * 56 + cg * 8);
        op[0] = make_float4(a0.x + s0.y + bv, a0.y + s1.x + bv,
                            a1.x + s1.y + bv, a1.y + s2.x + bv);
        op[1] = make_float4(a2.x + s2.y + bv, a2.y + s3.x + bv,
                            a3.x + s3.y + bv, a3.y + s4.x + bv);
    }
}

// ---------------------------------------------------------------------------
extern "C" void kernel_launch(void* const* d_in, const int* in_sizes, int n_in,
                              void* d_out, int out_size) {
    const float* x1    = (const float*)d_in[0];
    const float* dw1_w = (const float*)d_in[1];
    const float* dw1_g = (const float*)d_in[2];
    const float* dw1_b = (const float*)d_in[3];
    const float* dw1_m = (const float*)d_in[4];
    const float* dw1_v = (const float*)d_in[5];
    const float* dw2_w = (const float*)d_in[6];
    const float* dw2_g = (const float*)d_in[7];
    const float* dw2_b = (const float*)d_in[8];
    const float* dw2_m = (const float*)d_in[9];
    const float* dw2_v = (const float*)d_in[10];
    const float* weight1 = (const float*)d_in[11];
    const float* bias1   = (const float*)d_in[12];
    const float* pw1 = (const float*)d_in[13];
    const float* pb1 = (const float*)d_in[14];
    const float* pw2 = (const float*)d_in[15];
    const float* pb2 = (const float*)d_in[16];
    float* out = (float*)d_out;

    k_fuse<<<NPLANES * 2 + 590, 224>>>(x1, dw1_w, dw1_g, dw1_b, dw1_m, dw1_v,
                                       dw2_w, dw2_g, dw2_b, dw2_m, dw2_v,
                                       pw1, pw2, weight1);
    k_dyn_h<<<dim3(5, NB), 256>>>(pb1);
    k_dyn2<<<dim3(8, NB), 256>>>(pb2, bias1);
    k_conv<<<NPLANES * 2, 224>>>(out);
}

// round 16
// speedup vs baseline: 1.5743x; 1.5743x over previous
#include <cuda_runtime.h>
#include <math.h>

#define NB 16
#define NC 256
#define PLANE 3136
#define NPLANES 4096
typedef unsigned long long ull;

// scratch (static device globals; no allocation)
__device__ float g_xfuse[NPLANES * PLANE];   // 51.4 MB
__device__ float g_pool2[NB * 2 * 28 * NC];  // partial pools [b][half][bin][c]
__device__ float g_h[NB * 50 * 64];          // hidden layer (pos 49 = mean)
__device__ float g_wdyn[NB * 49 * NC];       // [B][pos][C]
__device__ float g_bdyn[NB * NC];            // [B][C]
__device__ float g_pw1T[256 * 64];           // [k][o]
__device__ float g_pw2T[64 * 1024];          // [k][oc]
__device__ float g_w1T[49 * 1024];           // [pos][g*C+c]

__device__ __forceinline__ void ffma2(ull& d, ull a, ull b) {
    asm("fma.rn.f32x2 %0, %1, %2, %0;" : "+l"(d) : "l"(a), "l"(b));
}
__device__ __forceinline__ float2 u2f2(ull v) {
    float2 r;
    r.x = __uint_as_float((unsigned)v);
    r.y = __uint_as_float((unsigned)(v >> 32));
    return r;
}

// ---------------------------------------------------------------------------
// Kernel 1: fused dw3x3+BN (x2), relu6 gate, x_fuse, partial 7x7 pooling.
// HALF-PLANE blocks (224 thr, 28 rows, tile 30x66), lane = row (conflict-
// free LDS.64), po-recombine mainloop (R9-proven). Pool partials go to
// g_pool2[b][half][4x7 bins][c]; k_dyn_h combines the split pool row 3.
// Blocks >= 2*NPLANES perform the small weight transposes.
// ---------------------------------------------------------------------------
__global__ __launch_bounds__(224, 6) void k_fuse(
    const float* __restrict__ x1,
    const float* __restrict__ dw1_w, const float* __restrict__ dw1_g,
    const float* __restrict__ dw1_b, const float* __restrict__ dw1_m,
    const float* __restrict__ dw1_v,
    const float* __restrict__ dw2_w, const float* __restrict__ dw2_g,
    const float* __restrict__ dw2_b, const float* __restrict__ dw2_m,
    const float* __restrict__ dw2_v,
    const float* __restrict__ pw1, const float* __restrict__ pw2,
    const float* __restrict__ w1grp) {
    const int tid = threadIdx.x;

    if (blockIdx.x >= 2 * NPLANES) {       // transpose side-work
        int i = (blockIdx.x - 2 * NPLANES) * 224 + tid;
        if (i < 16384) {                   // pw1 [64,256] -> [256,64]
            int k = i >> 6, o = i & 63;
            g_pw1T[i] = pw1[o * 256 + k];
        } else if (i < 81920) {            // pw2 [1024,64] -> [64,1024]
            int j = i - 16384;
            int k = j >> 10, oc = j & 1023;
            g_pw2T[j] = pw2[oc * 64 + k];
        } else if (i < 132096) {           // weight1 [G*C,49] -> [49,G*C]
            int l = i - 81920;
            int pos = l / 1024, gc = l & 1023;
            g_w1T[l] = w1grp[gc * 49 + pos];
        }
        return;
    }

    __shared__ float s[30 * 66];           // half tile, halo 1, stride 66
    __shared__ float2 sw1[9], sw2[9];      // packed (w,w) weights
    __shared__ float partial[196];

    const int bp = blockIdx.x >> 1;
    const int half = blockIdx.x & 1;       // 0: rows 0..27, 1: rows 28..55
    const int b = bp >> 8, c = bp & 255;
    const int base = half * 28;

    // column halo: x in {0,57} for all 30 tile rows
    if (tid < 60) {
        int r = tid >> 1, x = (tid & 1) ? 57 : 0;
        s[r * 66 + x] = 0.f;
    }
    {
        const float4* __restrict__ xp4 =
            (const float4*)(x1 + (size_t)bp * PLANE);
        for (int idx = tid; idx < 420; idx += 224) {   // 30 rows x 14 f4
            int r = idx / 14, c4 = idx - r * 14;
            int gr = base - 1 + r;
            float4 v = make_float4(0.f, 0.f, 0.f, 0.f);
            if ((unsigned)gr < 56u) v = xp4[gr * 14 + c4];
            float* d = &s[r * 66 + 1 + c4 * 4];
            d[0] = v.x; d[1] = v.y; d[2] = v.z; d[3] = v.w;
        }
    }
    // BN-folded channel scalars
    const float s1 = dw1_g[c] * rsqrtf(dw1_v[c] + 1e-5f);
    const float s2 = dw2_g[c] * rsqrtf(dw2_v[c] + 1e-5f);
    const float bb1 = dw1_b[c] - dw1_m[c] * s1;
    const float bb2 = dw2_b[c] - dw2_m[c] * s2;
    if (tid < 9) {
        float wa = dw1_w[c * 9 + tid] * s1;
        float wb = dw2_w[c * 9 + tid] * s2;
        sw1[tid] = make_float2(wa, wa);
        sw2[tid] = make_float2(wb, wb);
    }
    __syncthreads();

    const int lane = tid & 31;
    const int cg = tid >> 5;               // 0..6
    if (lane < 28) {
        ull aA[4] = {0, 0, 0, 0}, aB[4] = {0, 0, 0, 0};
#pragma unroll
        for (int ky = 0; ky < 3; ky++) {
            const float* rp = &s[(lane + ky) * 66 + cg * 8];
            ull pe[5];
#pragma unroll
            for (int k = 0; k < 5; k++) pe[k] = *(const ull*)(rp + 2 * k);
            ull po[4];
#pragma unroll
            for (int m = 0; m < 4; m++)
                po[m] = (pe[m] >> 32) | (pe[m + 1] << 32);
#pragma unroll
            for (int t = 0; t < 2; t++) {   // kx = 0, 2
                ull wa = *(const ull*)&sw1[ky * 3 + 2 * t];
                ull wb = *(const ull*)&sw2[ky * 3 + 2 * t];
#pragma unroll
                for (int j = 0; j < 4; j++) {
                    ffma2(aA[j], wa, pe[j + t]);
                    ffma2(aB[j], wb, pe[j + t]);
                }
            }
            {                               // kx = 1
                ull wa = *(const ull*)&sw1[ky * 3 + 1];
                ull wb = *(const ull*)&sw2[ky * 3 + 1];
#pragma unroll
                for (int j = 0; j < 4; j++) {
                    ffma2(aA[j], wa, po[j]);
                    ffma2(aB[j], wb, po[j]);
                }
            }
        }
        float f[8];
        float rsum = 0.f;
#pragma unroll
        for (int j = 0; j < 4; j++) {
            float2 pa = u2f2(aA[j]), pb = u2f2(aB[j]);
            float a0 = fminf(fmaxf(pa.x + bb1, 0.f), 6.f);
            float a1 = fminf(fmaxf(pa.y + bb1, 0.f), 6.f);
            float v0 = a0 * (pb.x + bb2);
            float v1 = a1 * (pb.y + bb2);
            f[2 * j] = v0; f[2 * j + 1] = v1;
            rsum += v0 + v1;
        }
        const int row = base + lane;
        float4* op = (float4*)(g_xfuse + (size_t)bp * PLANE + row * 56 + cg * 8);
        op[0] = make_float4(f[0], f[1], f[2], f[3]);
        op[1] = make_float4(f[4], f[5], f[6], f[7]);
        partial[lane * 7 + cg] = rsum;
    }
    __syncthreads();

    // partial pooling: 28 bins (4 local pool rows x 7 cols)
    if (tid < 28) {
        const int p = tid / 7, pc = tid - p * 7;
        int start, cnt;
        if (half == 0) { start = p * 8;                cnt = (p < 3) ? 8 : 4; }
        else           { start = (p == 0) ? 0 : p * 8 - 4; cnt = (p == 0) ? 4 : 8; }
        float sm = 0.f;
        for (int i = 0; i < cnt; i++) sm += partial[(start + i) * 7 + pc];
        g_pool2[((b * 2 + half) * 28 + tid) * NC + c] = sm;
    }
}

// ---------------------------------------------------------------------------
// Kernel 2a: hidden layer h = gelu(pw1 @ v + pb1) for all (b, pos).
// Combines the two pool halves (pool row 3 spans both).
// ---------------------------------------------------------------------------
__global__ __launch_bounds__(256) void k_dyn_h(const float* __restrict__ pb1) {
    __shared__ float v[10 * 256];

    const int pg = blockIdx.x, b = blockIdx.y, t = threadIdx.x;
    const int base = pg * 10;
    const int nload = (pg == 4) ? 9 : 10;

    for (int i = t; i < nload * 256; i += 256) {
        int pos = base + i / 256;
        int cc = i & 255;
        int pr = pos / 7, pc = pos - pr * 7;
        float val = 0.f;
        if (pr <= 3) val += g_pool2[((b * 2 + 0) * 28 + pr * 7 + pc) * NC + cc];
        if (pr >= 3) val += g_pool2[((b * 2 + 1) * 28 + (pr - 3) * 7 + pc) * NC + cc];
        v[i] = val * (1.f / 64.f);
    }
    if (pg == 4) {
        float sm = 0.f;
        for (int j = 0; j < 28; j++)
            sm += g_pool2[((b * 2 + 0) * 28 + j) * NC + t] +
                  g_pool2[((b * 2 + 1) * 28 + j) * NC + t];
        v[9 * 256 + t] = sm * (1.f / (64.f * 49.f));
    }
    __syncthreads();

    const int o = t & 63;
    for (int pl = t >> 6; pl < 10; pl += 4) {
        const float* vr = &v[pl * 256];
        float acc0 = 0.f, acc1 = 0.f;
#pragma unroll 8
        for (int k = 0; k < 256; k += 2) {
            acc0 += g_pw1T[k * 64 + o] * vr[k];
            acc1 += g_pw1T[(k + 1) * 64 + o] * vr[k + 1];
        }
        float x = acc0 + acc1 + pb1[o];
        g_h[(b * 50 + base + pl) * 64 + o] =
            0.5f * x * (1.f + erff(x * 0.70710678118654752f));
    }
}

// ---------------------------------------------------------------------------
// Kernel 2b: logits = h @ pw2 (+pb2), softmax over G, weighted sums.
// ---------------------------------------------------------------------------
__global__ __launch_bounds__(256) void k_dyn2(
    const float* __restrict__ pb2, const float* __restrict__ bias1) {
    __shared__ float hs[50 * 64];

    const int b = blockIdx.y, t = threadIdx.x;
    const int c = blockIdx.x * 32 + (t & 31);
    const int ps = t >> 5;                 // 0..7 pos stripe

    for (int i = t; i < 3200; i += 256) hs[i] = g_h[b * 3200 + i];
    __syncthreads();

    const int np = (ps < 2) ? 7 : 6;       // positions ps, ps+8, ...
    float acc[7][4];
#pragma unroll
    for (int i = 0; i < 7; i++)
#pragma unroll
        for (int g = 0; g < 4; g++) acc[i][g] = 0.f;

#pragma unroll 4
    for (int k = 0; k < 64; k++) {
        const float w0 = g_pw2T[k * 1024 + c];
        const float w1 = g_pw2T[k * 1024 + 256 + c];
        const float w2 = g_pw2T[k * 1024 + 512 + c];
        const float w3 = g_pw2T[k * 1024 + 768 + c];
#pragma unroll
        for (int i = 0; i < 7; i++) {
            if (i < np) {
                const float h = hs[(ps + 8 * i) * 64 + k];
                acc[i][0] += h * w0;
                acc[i][1] += h * w1;
                acc[i][2] += h * w2;
                acc[i][3] += h * w3;
            }
        }
    }

    const float q0 = pb2[c], q1 = pb2[256 + c], q2 = pb2[512 + c], q3 = pb2[768 + c];
#pragma unroll
    for (int i = 0; i < 7; i++) {
        if (i >= np) break;
        const int pos = ps + 8 * i;
        float l0 = acc[i][0] + q0, l1 = acc[i][1] + q1;
        float l2 = acc[i][2] + q2, l3 = acc[i][3] + q3;
        float m = fmaxf(fmaxf(l0, l1), fmaxf(l2, l3));
        float e0 = expf(l0 - m), e1 = expf(l1 - m);
        float e2 = expf(l2 - m), e3 = expf(l3 - m);
        float inv = 1.f / (e0 + e1 + e2 + e3);
        if (pos < 49) {
            const float* wp = &g_w1T[pos * 1024];
            float wv = e0 * wp[c] + e1 * wp[256 + c] + e2 * wp[512 + c] +
                       e3 * wp[768 + c];
            g_wdyn[(b * 49 + pos) * NC + c] = wv * inv;
        } else {
            float bv = e0 * bias1[c] + e1 * bias1[256 + c] +
                       e2 * bias1[512 + c] + e3 * bias1[768 + c];
            g_bdyn[b * NC + c] = bv * inv;
        }
    }
}

// ---------------------------------------------------------------------------
// Kernel 3: dynamic 7x7 depthwise conv + dynamic bias. Half-plane blocks,
// fp32 tile (fp16 reverted: cvt cost made it issue-bound), conflict-free
// lane=row LDS.64, S-accumulators, vectorized weight fetch (stride-8 wsm2).
// ---------------------------------------------------------------------------
__global__ __launch_bounds__(224, 6) void k_conv(float* __restrict__ out) {
    __shared__ float s[34 * 66];           // half tile, halo 3, stride 66
    __shared__ __align__(16) float2 wsm2[56];  // (w,w), stride 8 per ky row
    __shared__ float bsm;

    const int bp = blockIdx.x >> 1;        // plane
    const int half = blockIdx.x & 1;       // 0: rows 0..27, 1: rows 28..55
    const int b = bp >> 8, c = bp & 255;
    const int base = half * 28;
    const int tid = threadIdx.x;

    // column-halo zeroing: cols {0,1,2,59,60,61} x 34 rows = 204 cells
    if (tid < 204) {
        int r = tid / 6, xs = tid - r * 6;
        int x = (xs < 3) ? xs : 56 + xs;
        s[r * 66 + x] = 0.f;
    }
    {
        const float4* __restrict__ xp4 =
            (const float4*)(g_xfuse + (size_t)bp * PLANE);
        for (int idx = tid; idx < 476; idx += 224) {   // 34 rows x 14 f4
            int r = idx / 14, c4 = idx - r * 14;
            int gr = base - 3 + r;
            float4 v = make_float4(0.f, 0.f, 0.f, 0.f);
            if ((unsigned)gr < 56u) v = xp4[gr * 14 + c4];
            float* d = &s[r * 66 + 3 + c4 * 4];
            d[0] = v.x; d[1] = v.y; d[2] = v.z; d[3] = v.w;
        }
    }
    if (tid < 49) {
        int ky = tid / 7, kx = tid - ky * 7;
        float w = g_wdyn[(b * 49 + tid) * NC + c];
        wsm2[ky * 8 + kx] = make_float2(w, w);
    }
    if (tid == 63) bsm = g_bdyn[b * NC + c];
    __syncthreads();

    const int lane = tid & 31;
    const int cg = tid >> 5;               // 0..6
    if (lane < 28) {
        const int row = base + lane;       // output row (global)
        ull acc[4] = {0, 0, 0, 0};
        ull S[5] = {0, 0, 0, 0, 0};
#pragma unroll
        for (int ky = 0; ky < 7; ky++) {
            const float* rp = &s[(lane + ky) * 66 + cg * 8];
            ull pe[7];
#pragma unroll
            for (int k = 0; k < 7; k++) pe[k] = *(const ull*)(rp + 2 * k);
            // vectorized weight fetch: kx pairs (0,1) (2,3) (4,5) + 6
            ulonglong2 wq0 = *(const ulonglong2*)&wsm2[ky * 8 + 0];
            ulonglong2 wq1 = *(const ulonglong2*)&wsm2[ky * 8 + 2];
            ulonglong2 wq2 = *(const ulonglong2*)&wsm2[ky * 8 + 4];
            ull w6 = *(const ull*)&wsm2[ky * 8 + 6];
            ull we[4] = {wq0.x, wq1.x, wq2.x, w6};    // kx = 0,2,4,6
            ull wo[3] = {wq0.y, wq1.y, wq2.y};        // kx = 1,3,5
#pragma unroll
            for (int t = 0; t < 4; t++)
#pragma unroll
                for (int j = 0; j < 4; j++) ffma2(acc[j], we[t], pe[j + t]);
#pragma unroll
            for (int t = 0; t < 3; t++)
#pragma unroll
                for (int i = 0; i < 5; i++) ffma2(S[i], wo[t], pe[i + t]);
        }
        const float bv = bsm;
        float2 a0 = u2f2(acc[0]), a1 = u2f2(acc[1]);
        float2 a2 = u2f2(acc[2]), a3 = u2f2(acc[3]);
        float2 s0 = u2f2(S[0]), s1 = u2f2(S[1]), s2 = u2f2(S[2]);
        float2 s3 = u2f2(S[3]), s4 = u2f2(S[4]);
        float4* op = (float4*)(out + (size_t)bp * PLANE + row * 56 + cg * 8);
        op[0] = make_float4(a0.x + s0.y + bv, a0.y + s1.x + bv,
                            a1.x + s1.y + bv, a1.y + s2.x + bv);
        op[1] = make_float4(a2.x + s2.y + bv, a2.y + s3.x + bv,
                            a3.x + s3.y + bv, a3.y + s4.x + bv);
    }
}

// ---------------------------------------------------------------------------
extern "C" void kernel_launch(void* const* d_in, const int* in_sizes, int n_in,
                              void* d_out, int out_size) {
    const float* x1    = (const float*)d_in[0];
    const float* dw1_w = (const float*)d_in[1];
    const float* dw1_g = (const float*)d_in[2];
    const float* dw1_b = (const float*)d_in[3];
    const float* dw1_m = (const float*)d_in[4];
    const float* dw1_v = (const float*)d_in[5];
    const float* dw2_w = (const float*)d_in[6];
    const float* dw2_g = (const float*)d_in[7];
    const float* dw2_b = (const float*)d_in[8];
    const float* dw2_m = (const float*)d_in[9];
    const float* dw2_v = (const float*)d_in[10];
    const float* weight1 = (const float*)d_in[11];
    const float* bias1   = (const float*)d_in[12];
    const float* pw1 = (const float*)d_in[13];
    const float* pb1 = (const float*)d_in[14];
    const float* pw2 = (const float*)d_in[15];
    const float* pb2 = (const float*)d_in[16];
    float* out = (float*)d_out;

    k_fuse<<<NPLANES * 2 + 590, 224>>>(x1, dw1_w, dw1_g, dw1_b, dw1_m, dw1_v,
                                       dw2_w, dw2_g, dw2_b, dw2_m, dw2_v,
                                       pw1, pw2, weight1);
    k_dyn_h<<<dim3(5, NB), 256>>>(pb1);
    k_dyn2<<<dim3(8, NB), 256>>>(pb2, bias1);
    k_conv<<<NPLANES * 2, 224>>>(out);
}

// round 17
// speedup vs baseline: 1.6079x; 1.0214x over previous
#include <cuda_runtime.h>
#include <math.h>

#define NB 16
#define NC 256
#define PLANE 3136
#define NPLANES 4096
typedef unsigned long long ull;

// scratch (static device globals; no allocation)
__device__ float g_xfuse[NPLANES * PLANE];   // 51.4 MB
__device__ float g_pool2[NB * 2 * 28 * NC];  // partial pools [b][half][bin][c]
__device__ float g_h[NB * 50 * 64];          // hidden layer (pos 49 = mean)
__device__ float g_wdyn[NB * 49 * NC];       // [B][pos][C]
__device__ float g_bdyn[NB * NC];            // [B][C]
__device__ float g_pw1T[256 * 64];           // [k][o]
__device__ float g_pw2T[64 * 1024];          // [k][oc]
__device__ float g_w1T[49 * 1024];           // [pos][g*C+c]

__device__ __forceinline__ void ffma2(ull& d, ull a, ull b) {
    asm("fma.rn.f32x2 %0, %1, %2, %0;" : "+l"(d) : "l"(a), "l"(b));
}
__device__ __forceinline__ float2 u2f2(ull v) {
    float2 r;
    r.x = __uint_as_float((unsigned)v);
    r.y = __uint_as_float((unsigned)(v >> 32));
    return r;
}

// ---------------------------------------------------------------------------
// Kernel 1: fused dw3x3+BN (x2), relu6 gate, x_fuse, partial 7x7 pooling.
// HALF-PLANE blocks. MLP-batched prologue: all LDGs (2 tile f4 + 10 BN
// scalars + 2 weight rows) issue back-to-back BEFORE any dependent STS, so
// one latency exposure instead of two serialized ones.
// Blocks >= 2*NPLANES perform the small weight transposes.
// ---------------------------------------------------------------------------
__global__ __launch_bounds__(224, 6) void k_fuse(
    const float* __restrict__ x1,
    const float* __restrict__ dw1_w, const float* __restrict__ dw1_g,
    const float* __restrict__ dw1_b, const float* __restrict__ dw1_m,
    const float* __restrict__ dw1_v,
    const float* __restrict__ dw2_w, const float* __restrict__ dw2_g,
    const float* __restrict__ dw2_b, const float* __restrict__ dw2_m,
    const float* __restrict__ dw2_v,
    const float* __restrict__ pw1, const float* __restrict__ pw2,
    const float* __restrict__ w1grp) {
    const int tid = threadIdx.x;

    if (blockIdx.x >= 2 * NPLANES) {       // transpose side-work
        int i = (blockIdx.x - 2 * NPLANES) * 224 + tid;
        if (i < 16384) {                   // pw1 [64,256] -> [256,64]
            int k = i >> 6, o = i & 63;
            g_pw1T[i] = pw1[o * 256 + k];
        } else if (i < 81920) {            // pw2 [1024,64] -> [64,1024]
            int j = i - 16384;
            int k = j >> 10, oc = j & 1023;
            g_pw2T[j] = pw2[oc * 64 + k];
        } else if (i < 132096) {           // weight1 [G*C,49] -> [49,G*C]
            int l = i - 81920;
            int pos = l / 1024, gc = l & 1023;
            g_w1T[l] = w1grp[gc * 49 + pos];
        }
        return;
    }

    __shared__ float s[30 * 66];           // half tile, halo 1, stride 66
    __shared__ float2 sw1[9], sw2[9];      // packed (w,w) weights
    __shared__ float partial[196];

    const int bp = blockIdx.x >> 1;
    const int half = blockIdx.x & 1;       // 0: rows 0..27, 1: rows 28..55
    const int b = bp >> 8, c = bp & 255;
    const int base = half * 28;

    // ---- batched load issue: ALL global loads before any dependent STS ----
    const float4* __restrict__ xp4 = (const float4*)(x1 + (size_t)bp * PLANE);
    const int i0 = tid, i1 = tid + 224;    // 420 f4 total: i1 valid if <420
    const int r0i = i0 / 14, c40 = i0 - r0i * 14;
    const int r1i = i1 / 14, c41 = i1 - r1i * 14;
    const int gr0 = base - 1 + r0i, gr1 = base - 1 + r1i;
    const bool has1 = (i1 < 420);
    float4 v0 = make_float4(0.f, 0.f, 0.f, 0.f);
    float4 v1 = make_float4(0.f, 0.f, 0.f, 0.f);
    if ((unsigned)gr0 < 56u) v0 = xp4[gr0 * 14 + c40];
    if (has1 && (unsigned)gr1 < 56u) v1 = xp4[gr1 * 14 + c41];
    // BN scalar loads (independent; overlap the tile loads in flight)
    const float G1 = dw1_g[c], VV1 = dw1_v[c], B1 = dw1_b[c], M1 = dw1_m[c];
    const float G2 = dw2_g[c], VV2 = dw2_v[c], B2 = dw2_b[c], M2 = dw2_m[c];
    float wr1 = 0.f, wr2 = 0.f;
    if (tid < 9) { wr1 = dw1_w[c * 9 + tid]; wr2 = dw2_w[c * 9 + tid]; }

    // halo zero (no load deps; issues while LDGs are in flight)
    if (tid < 60) {
        int r = tid >> 1, x = (tid & 1) ? 57 : 0;
        s[r * 66 + x] = 0.f;
    }
    // dependent STS
    {
        float* d0 = &s[r0i * 66 + 1 + c40 * 4];
        d0[0] = v0.x; d0[1] = v0.y; d0[2] = v0.z; d0[3] = v0.w;
        if (has1) {
            float* d1 = &s[r1i * 66 + 1 + c41 * 4];
            d1[0] = v1.x; d1[1] = v1.y; d1[2] = v1.z; d1[3] = v1.w;
        }
    }
    // BN-folded channel scalars
    const float s1 = G1 * rsqrtf(VV1 + 1e-5f);
    const float s2 = G2 * rsqrtf(VV2 + 1e-5f);
    const float bb1 = B1 - M1 * s1;
    const float bb2 = B2 - M2 * s2;
    if (tid < 9) {
        float wa = wr1 * s1, wb = wr2 * s2;
        sw1[tid] = make_float2(wa, wa);
        sw2[tid] = make_float2(wb, wb);
    }
    __syncthreads();

    const int lane = tid & 31;
    const int cg = tid >> 5;               // 0..6
    if (lane < 28) {
        ull aA[4] = {0, 0, 0, 0}, aB[4] = {0, 0, 0, 0};
#pragma unroll
        for (int ky = 0; ky < 3; ky++) {
            const float* rp = &s[(lane + ky) * 66 + cg * 8];
            ull pe[5];
#pragma unroll
            for (int k = 0; k < 5; k++) pe[k] = *(const ull*)(rp + 2 * k);
            ull po[4];
#pragma unroll
            for (int m = 0; m < 4; m++)
                po[m] = (pe[m] >> 32) | (pe[m + 1] << 32);
#pragma unroll
            for (int t = 0; t < 2; t++) {   // kx = 0, 2
                ull wa = *(const ull*)&sw1[ky * 3 + 2 * t];
                ull wb = *(const ull*)&sw2[ky * 3 + 2 * t];
#pragma unroll
                for (int j = 0; j < 4; j++) {
                    ffma2(aA[j], wa, pe[j + t]);
                    ffma2(aB[j], wb, pe[j + t]);
                }
            }
            {                               // kx = 1
                ull wa = *(const ull*)&sw1[ky * 3 + 1];
                ull wb = *(const ull*)&sw2[ky * 3 + 1];
#pragma unroll
                for (int j = 0; j < 4; j++) {
                    ffma2(aA[j], wa, po[j]);
                    ffma2(aB[j], wb, po[j]);
                }
            }
        }
        float f[8];
        float rsum = 0.f;
#pragma unroll
        for (int j = 0; j < 4; j++) {
            float2 pa = u2f2(aA[j]), pb = u2f2(aB[j]);
            float a0 = fminf(fmaxf(pa.x + bb1, 0.f), 6.f);
            float a1 = fminf(fmaxf(pa.y + bb1, 0.f), 6.f);
            float v0f = a0 * (pb.x + bb2);
            float v1f = a1 * (pb.y + bb2);
            f[2 * j] = v0f; f[2 * j + 1] = v1f;
            rsum += v0f + v1f;
        }
        const int row = base + lane;
        float4* op = (float4*)(g_xfuse + (size_t)bp * PLANE + row * 56 + cg * 8);
        op[0] = make_float4(f[0], f[1], f[2], f[3]);
        op[1] = make_float4(f[4], f[5], f[6], f[7]);
        partial[lane * 7 + cg] = rsum;
    }
    __syncthreads();

    // partial pooling: 28 bins (4 local pool rows x 7 cols)
    if (tid < 28) {
        const int p = tid / 7, pc = tid - p * 7;
        int start, cnt;
        if (half == 0) { start = p * 8;                cnt = (p < 3) ? 8 : 4; }
        else           { start = (p == 0) ? 0 : p * 8 - 4; cnt = (p == 0) ? 4 : 8; }
        float sm = 0.f;
        for (int i = 0; i < cnt; i++) sm += partial[(start + i) * 7 + pc];
        g_pool2[((b * 2 + half) * 28 + tid) * NC + c] = sm;
    }
}

// ---------------------------------------------------------------------------
// Kernel 2a: hidden layer h = gelu(pw1 @ v + pb1) for all (b, pos).
// Combines the two pool halves (pool row 3 spans both).
// ---------------------------------------------------------------------------
__global__ __launch_bounds__(256) void k_dyn_h(const float* __restrict__ pb1) {
    __shared__ float v[10 * 256];

    const int pg = blockIdx.x, b = blockIdx.y, t = threadIdx.x;
    const int base = pg * 10;
    const int nload = (pg == 4) ? 9 : 10;

    for (int i = t; i < nload * 256; i += 256) {
        int pos = base + i / 256;
        int cc = i & 255;
        int pr = pos / 7, pc = pos - pr * 7;
        float val = 0.f;
        if (pr <= 3) val += g_pool2[((b * 2 + 0) * 28 + pr * 7 + pc) * NC + cc];
        if (pr >= 3) val += g_pool2[((b * 2 + 1) * 28 + (pr - 3) * 7 + pc) * NC + cc];
        v[i] = val * (1.f / 64.f);
    }
    if (pg == 4) {
        float sm = 0.f;
        for (int j = 0; j < 28; j++)
            sm += g_pool2[((b * 2 + 0) * 28 + j) * NC + t] +
                  g_pool2[((b * 2 + 1) * 28 + j) * NC + t];
        v[9 * 256 + t] = sm * (1.f / (64.f * 49.f));
    }
    __syncthreads();

    const int o = t & 63;
    for (int pl = t >> 6; pl < 10; pl += 4) {
        const float* vr = &v[pl * 256];
        float acc0 = 0.f, acc1 = 0.f;
#pragma unroll 8
        for (int k = 0; k < 256; k += 2) {
            acc0 += g_pw1T[k * 64 + o] * vr[k];
            acc1 += g_pw1T[(k + 1) * 64 + o] * vr[k + 1];
        }
        float x = acc0 + acc1 + pb1[o];
        g_h[(b * 50 + base + pl) * 64 + o] =
            0.5f * x * (1.f + erff(x * 0.70710678118654752f));
    }
}

// ---------------------------------------------------------------------------
// Kernel 2b: logits = h @ pw2 (+pb2), softmax over G, weighted sums.
// ---------------------------------------------------------------------------
__global__ __launch_bounds__(256) void k_dyn2(
    const float* __restrict__ pb2, const float* __restrict__ bias1) {
    __shared__ float hs[50 * 64];

    const int b = blockIdx.y, t = threadIdx.x;
    const int c = blockIdx.x * 32 + (t & 31);
    const int ps = t >> 5;                 // 0..7 pos stripe

    for (int i = t; i < 3200; i += 256) hs[i] = g_h[b * 3200 + i];
    __syncthreads();

    const int np = (ps < 2) ? 7 : 6;       // positions ps, ps+8, ...
    float acc[7][4];
#pragma unroll
    for (int i = 0; i < 7; i++)
#pragma unroll
        for (int g = 0; g < 4; g++) acc[i][g] = 0.f;

#pragma unroll 4
    for (int k = 0; k < 64; k++) {
        const float w0 = g_pw2T[k * 1024 + c];
        const float w1 = g_pw2T[k * 1024 + 256 + c];
        const float w2 = g_pw2T[k * 1024 + 512 + c];
        const float w3 = g_pw2T[k * 1024 + 768 + c];
#pragma unroll
        for (int i = 0; i < 7; i++) {
            if (i < np) {
                const float h = hs[(ps + 8 * i) * 64 + k];
                acc[i][0] += h * w0;
                acc[i][1] += h * w1;
                acc[i][2] += h * w2;
                acc[i][3] += h * w3;
            }
        }
    }

    const float q0 = pb2[c], q1 = pb2[256 + c], q2 = pb2[512 + c], q3 = pb2[768 + c];
#pragma unroll
    for (int i = 0; i < 7; i++) {
        if (i >= np) break;
        const int pos = ps + 8 * i;
        float l0 = acc[i][0] + q0, l1 = acc[i][1] + q1;
        float l2 = acc[i][2] + q2, l3 = acc[i][3] + q3;
        float m = fmaxf(fmaxf(l0, l1), fmaxf(l2, l3));
        float e0 = expf(l0 - m), e1 = expf(l1 - m);
        float e2 = expf(l2 - m), e3 = expf(l3 - m);
        float inv = 1.f / (e0 + e1 + e2 + e3);
        if (pos < 49) {
            const float* wp = &g_w1T[pos * 1024];
            float wv = e0 * wp[c] + e1 * wp[256 + c] + e2 * wp[512 + c] +
                       e3 * wp[768 + c];
            g_wdyn[(b * 49 + pos) * NC + c] = wv * inv;
        } else {
            float bv = e0 * bias1[c] + e1 * bias1[256 + c] +
                       e2 * bias1[512 + c] + e3 * bias1[768 + c];
            g_bdyn[b * NC + c] = bv * inv;
        }
    }
}

// ---------------------------------------------------------------------------
// Kernel 3: dynamic 7x7 depthwise conv + dynamic bias. Half-plane blocks,
// conflict-free lane=row LDS.64, S-accumulators, vectorized weight fetch.
// MLP-batched prologue: all 3 tile LDG.128s + wdyn/bdyn scalars issue
// before any dependent STS (one latency exposure).
// ---------------------------------------------------------------------------
__global__ __launch_bounds__(224, 6) void k_conv(float* __restrict__ out) {
    __shared__ float s[34 * 66];           // half tile, halo 3, stride 66
    __shared__ __align__(16) float2 wsm2[56];  // (w,w), stride 8 per ky row
    __shared__ float bsm;

    const int bp = blockIdx.x >> 1;        // plane
    const int half = blockIdx.x & 1;       // 0: rows 0..27, 1: rows 28..55
    const int b = bp >> 8, c = bp & 255;
    const int base = half * 28;
    const int tid = threadIdx.x;

    // ---- batched load issue: ALL global loads before any dependent STS ----
    const float4* __restrict__ xp4 =
        (const float4*)(g_xfuse + (size_t)bp * PLANE);
    const int i0 = tid, i1 = tid + 224, i2 = tid + 448;  // 476 f4 total
    const int r0i = i0 / 14, c40 = i0 - r0i * 14;
    const int r1i = i1 / 14, c41 = i1 - r1i * 14;
    const int r2i = i2 / 14, c42 = i2 - r2i * 14;
    const int gr0 = base - 3 + r0i, gr1 = base - 3 + r1i, gr2 = base - 3 + r2i;
    const bool has2 = (i2 < 476);
    float4 v0 = make_float4(0.f, 0.f, 0.f, 0.f);
    float4 v1 = make_float4(0.f, 0.f, 0.f, 0.f);
    float4 v2 = make_float4(0.f, 0.f, 0.f, 0.f);
    if ((unsigned)gr0 < 56u) v0 = xp4[gr0 * 14 + c40];
    if ((unsigned)gr1 < 56u) v1 = xp4[gr1 * 14 + c41];
    if (has2 && (unsigned)gr2 < 56u) v2 = xp4[gr2 * 14 + c42];
    float wv = 0.f, bdv = 0.f;
    if (tid < 49) wv = g_wdyn[(b * 49 + tid) * NC + c];
    if (tid == 63) bdv = g_bdyn[b * NC + c];

    // halo zeroing (no load deps): cols {0,1,2,59,60,61} x 34 rows = 204
    if (tid < 204) {
        int r = tid / 6, xs = tid - r * 6;
        int x = (xs < 3) ? xs : 56 + xs;
        s[r * 66 + x] = 0.f;
    }
    // dependent STS
    {
        float* d0 = &s[r0i * 66 + 3 + c40 * 4];
        d0[0] = v0.x; d0[1] = v0.y; d0[2] = v0.z; d0[3] = v0.w;
        float* d1 = &s[r1i * 66 + 3 + c41 * 4];
        d1[0] = v1.x; d1[1] = v1.y; d1[2] = v1.z; d1[3] = v1.w;
        if (has2) {
            float* d2 = &s[r2i * 66 + 3 + c42 * 4];
            d2[0] = v2.x; d2[1] = v2.y; d2[2] = v2.z; d2[3] = v2.w;
        }
    }
    if (tid < 49) {
        int ky = tid / 7, kx = tid - ky * 7;
        wsm2[ky * 8 + kx] = make_float2(wv, wv);
    }
    if (tid == 63) bsm = bdv;
    __syncthreads();

    const int lane = tid & 31;
    const int cg = tid >> 5;               // 0..6
    if (lane < 28) {
        const int row = base + lane;       // output row (global)
        ull acc[4] = {0, 0, 0, 0};
        ull S[5] = {0, 0, 0, 0, 0};
#pragma unroll
        for (int ky = 0; ky < 7; ky++) {
            const float* rp = &s[(lane + ky) * 66 + cg * 8];
            ull pe[7];
#pragma unroll
            for (int k = 0; k < 7; k++) pe[k] = *(const ull*)(rp + 2 * k);
            // vectorized weight fetch: kx pairs (0,1) (2,3) (4,5) + 6
            ulonglong2 wq0 = *(const ulonglong2*)&wsm2[ky * 8 + 0];
            ulonglong2 wq1 = *(const ulonglong2*)&wsm2[ky * 8 + 2];
            ulonglong2 wq2 = *(const ulonglong2*)&wsm2[ky * 8 + 4];
            ull w6 = *(const ull*)&wsm2[ky * 8 + 6];
            ull we[4] = {wq0.x, wq1.x, wq2.x, w6};    // kx = 0,2,4,6
            ull wo[3] = {wq0.y, wq1.y, wq2.y};        // kx = 1,3,5
#pragma unroll
            for (int t = 0; t < 4; t++)
#pragma unroll
                for (int j = 0; j < 4; j++) ffma2(acc[j], we[t], pe[j + t]);
#pragma unroll
            for (int t = 0; t < 3; t++)
#pragma unroll
                for (int i = 0; i < 5; i++) ffma2(S[i], wo[t], pe[i + t]);
        }
        const float bv = bsm;
        float2 a0 = u2f2(acc[0]), a1 = u2f2(acc[1]);
        float2 a2 = u2f2(acc[2]), a3 = u2f2(acc[3]);
        float2 s0 = u2f2(S[0]), s1 = u2f2(S[1]), s2 = u2f2(S[2]);
        float2 s3 = u2f2(S[3]), s4 = u2f2(S[4]);
        float4* op = (float4*)(out + (size_t)bp * PLANE + row * 56 + cg * 8);
        op[0] = make_float4(a0.x + s0.y + bv, a0.y + s1.x + bv,
                            a1.x + s1.y + bv, a1.y + s2.x + bv);
        op[1] = make_float4(a2.x + s2.y + bv, a2.y + s3.x + bv,
                            a3.x + s3.y + bv, a3.y + s4.x + bv);
    }
}

// ---------------------------------------------------------------------------
extern "C" void kernel_launch(void* const* d_in, const int* in_sizes, int n_in,
                              void* d_out, int out_size) {
    const float* x1    = (const float*)d_in[0];
    const float* dw1_w = (const float*)d_in[1];
    const float* dw1_g = (const float*)d_in[2];
    const float* dw1_b = (const float*)d_in[3];
    const float* dw1_m = (const float*)d_in[4];
    const float* dw1_v = (const float*)d_in[5];
    const float* dw2_w = (const float*)d_in[6];
    const float* dw2_g = (const float*)d_in[7];
    const float* dw2_b = (const float*)d_in[8];
    const float* dw2_m = (const float*)d_in[9];
    const float* dw2_v = (const float*)d_in[10];
    const float* weight1 = (const float*)d_in[11];
    const float* bias1   = (const float*)d_in[12];
    const float* pw1 = (const float*)d_in[13];
    const float* pb1 = (const float*)d_in[14];
    const float* pw2 = (const float*)d_in[15];
    const float* pb2 = (const float*)d_in[16];
    float* out = (float*)d_out;

    k_fuse<<<NPLANES * 2 + 590, 224>>>(x1, dw1_w, dw1_g, dw1_b, dw1_m, dw1_v,
                                       dw2_w, dw2_g, dw2_b, dw2_m, dw2_v,
                                       pw1, pw2, weight1);
    k_dyn_h<<<dim3(5, NB), 256>>>(pb1);
    k_dyn2<<<dim3(8, NB), 256>>>(pb2, bias1);
    k_conv<<<NPLANES * 2, 224>>>(out);
}